// round 3
// baseline (speedup 1.0000x reference)
#include <cuda_runtime.h>
#include <cstdint>

#define N_PTS   16384
#define GRID    32
#define CELLS   (GRID * GRID * GRID)
#define LOF     (-5.0f)
#define CELL    0.3125f
#define INVCELL 3.2f
#define SUBQ    4          // threads cooperating per query

// Scratch (device globals — no allocations). Everything is fully rewritten
// each call: g_cnt zeroed by zero_kernel, g_start/g_cur rebuilt by scan,
// g_pts fully scattered, g_sq fully written by search. Graph-replay safe.
__device__ int    g_cnt[2][CELLS];
__device__ int    g_cur[2][CELLS];
__device__ int    g_start[2][CELLS + 1];
__device__ float4 g_pts[2][N_PTS];     // sorted-by-cell: (x, y, z, x^2+y^2+z^2)
__device__ float  g_sq[2][N_PTS];      // sqrt of min squared distance per query

__device__ __forceinline__ int cell_coord(float v) {
    int c = (int)((v - LOF) * INVCELL);
    return min(max(c, 0), GRID - 1);
}

__global__ void zero_kernel() {
    int i = blockIdx.x * blockDim.x + threadIdx.x;   // 65536 ints
    ((int*)g_cnt)[i] = 0;
}

__global__ void count_kernel(const float* __restrict__ sx,
                             const float* __restrict__ tg) {
    int idx = blockIdx.x * blockDim.x + threadIdx.x;
    int cl = idx >> 14, i = idx & (N_PTS - 1);
    const float* p = cl ? tg : sx;      // cloud 0 = state_x, cloud 1 = target
    float x = p[3 * i], y = p[3 * i + 1], z = p[3 * i + 2];
    int cid = (cell_coord(z) << 10) | (cell_coord(y) << 5) | cell_coord(x);
    atomicAdd(&g_cnt[cl][cid], 1);
}

__global__ __launch_bounds__(1024) void scan_kernel() {
    __shared__ int sh[1024];
    const int cl = blockIdx.x;
    const int t = threadIdx.x;
    const int base = t * 32;
    int loc[32];
    int sum = 0;
    #pragma unroll
    for (int k = 0; k < 32; k++) { loc[k] = g_cnt[cl][base + k]; sum += loc[k]; }
    sh[t] = sum;
    __syncthreads();
    for (int off = 1; off < 1024; off <<= 1) {       // Hillis-Steele inclusive
        int v = (t >= off) ? sh[t - off] : 0;
        __syncthreads();
        sh[t] += v;
        __syncthreads();
    }
    int run = sh[t] - sum;                            // exclusive prefix
    #pragma unroll
    for (int k = 0; k < 32; k++) {
        g_start[cl][base + k] = run;
        g_cur[cl][base + k] = run;
        run += loc[k];
    }
    if (t == 1023) g_start[cl][CELLS] = run;          // == N_PTS
}

__global__ void scatter_kernel(const float* __restrict__ sx,
                               const float* __restrict__ tg) {
    int idx = blockIdx.x * blockDim.x + threadIdx.x;
    int cl = idx >> 14, i = idx & (N_PTS - 1);
    const float* p = cl ? tg : sx;
    float x = p[3 * i], y = p[3 * i + 1], z = p[3 * i + 2];
    int cid = (cell_coord(z) << 10) | (cell_coord(y) << 5) | cell_coord(x);
    int pos = atomicAdd(&g_cur[cl][cid], 1);
    g_pts[cl][pos] = make_float4(x, y, z, x * x + y * y + z * z);
}

// One query per 4-thread quad. Queries come from the sorted array, so
// adjacent threads walk the same cells (coherent control flow + L1 reuse).
__global__ __launch_bounds__(256) void search_kernel() {
    const int gtid = blockIdx.x * 256 + threadIdx.x;
    const int qcl = blockIdx.y;           // query cloud
    const int rcl = qcl ^ 1;              // reference cloud
    const int qid = gtid >> 2;
    const int sub = gtid & 3;
    const unsigned qmask = 0xFu << (threadIdx.x & 28);  // this quad's lanes

    const float4 q = g_pts[qcl][qid];
    const float nax = -2.0f * q.x, nay = -2.0f * q.y, naz = -2.0f * q.z;
    const float a2 = q.w;
    const int cx = cell_coord(q.x), cy = cell_coord(q.y), cz = cell_coord(q.z);

    const float4* __restrict__ ref = g_pts[rcl];
    const int* __restrict__ st = g_start[rcl];

    float m = __int_as_float(0x7f800000);   // +inf
    int r = 0;
    while (true) {
        // scan Chebyshev shell r
        for (int dz = -r; dz <= r; dz++) {
            int z = cz + dz;
            if ((unsigned)z >= GRID) continue;
            for (int dy = -r; dy <= r; dy++) {
                int y = cy + dy;
                if ((unsigned)y >= GRID) continue;
                int zy = (z << 10) | (y << 5);
                bool edge = (dz == -r) | (dz == r) | (dy == -r) | (dy == r);
                int xstep = edge ? 1 : 2 * r;   // interior rows: only x = ±r
                for (int dx = -r; dx <= r; dx += xstep) {
                    int x = cx + dx;
                    if ((unsigned)x >= GRID) continue;
                    int cid = zy | x;
                    int e = st[cid + 1];
                    for (int p = st[cid] + sub; p < e; p += SUBQ) {
                        float4 t = ref[p];
                        float d = fmaf(naz, t.z, t.w);
                        d = fmaf(nay, t.y, d);
                        d = fmaf(nax, t.x, d);
                        m = fminf(m, d);
                    }
                }
            }
        }
        // combine quad partial mins (quad lanes are convergent here)
        m = fminf(m, __shfl_xor_sync(qmask, m, 1));
        m = fminf(m, __shfl_xor_sync(qmask, m, 2));
        // all cells with Chebyshev <= r scanned -> unscanned pts >= r*CELL away
        float best = fmaxf(a2 + m, 0.0f);
        float bound = (float)r * CELL;
        if (best <= bound * bound || r >= GRID - 1) break;
        r++;
    }
    if (sub == 0) g_sq[qcl][qid] = sqrtf(fmaxf(a2 + m, 0.0f));
}

__global__ __launch_bounds__(1024) void reduce_kernel(float* __restrict__ out) {
    __shared__ float red[1024];
    const int tid = threadIdx.x;
    const float4* v = (const float4*)g_sq;   // 32768 floats = 8192 float4
    float s = 0.0f;
    #pragma unroll
    for (int k = 0; k < 8; k++) {
        float4 t = v[tid + k * 1024];
        s += (t.x + t.y) + (t.z + t.w);
    }
    red[tid] = s;
    __syncthreads();
    #pragma unroll
    for (int off = 512; off > 0; off >>= 1) {
        if (tid < off) red[tid] += red[tid + off];
        __syncthreads();
    }
    if (tid == 0)
        out[0] = red[0] * (5.0f / (float)N_PTS);   // (mean1+mean2)*0.5*10
}

extern "C" void kernel_launch(void* const* d_in, const int* in_sizes, int n_in,
                              void* d_out, int out_size) {
    const float* state_x = (const float*)d_in[0];
    const float* target  = (const float*)d_in[1];

    zero_kernel<<<64, 1024>>>();
    count_kernel<<<(2 * N_PTS) / 256, 256>>>(state_x, target);
    scan_kernel<<<2, 1024>>>();
    scatter_kernel<<<(2 * N_PTS) / 256, 256>>>(state_x, target);

    dim3 sgrid((N_PTS * SUBQ) / 256, 2);
    search_kernel<<<sgrid, 256>>>();

    reduce_kernel<<<1, 1024>>>((float*)d_out);
}

// round 4
// speedup vs baseline: 1.4318x; 1.4318x over previous
#include <cuda_runtime.h>
#include <cstdint>

#define N_PTS   16384
#define GRIDD   32
#define CELLS   (GRIDD * GRIDD * GRIDD)
#define LOF     (-5.0f)
#define CELL    0.3125f
#define INVCELL 3.2f
#define SUBQ    4          // threads cooperating per query

// Scratch in device globals (no runtime allocation).
// INVARIANT: g_cnt == 0 on entry to count_kernel. True at load (zero-init)
// and restored by scan_kernel (zeroes counts after reading them), so every
// graph replay sees the same initial state. No separate zero kernel.
__device__ int    g_cnt[2][CELLS];
__device__ int    g_cur[2][CELLS];
__device__ int    g_start[2][CELLS + 1];
__device__ float4 g_pts[2][N_PTS];     // sorted by cell: (x, y, z, |p|^2)
__device__ float  g_sq[2][N_PTS];      // sqrt(min sq dist) per query

__device__ __forceinline__ int cell_coord(float v) {
    int c = (int)((v - LOF) * INVCELL);
    return min(max(c, 0), GRIDD - 1);
}

__global__ void count_kernel(const float* __restrict__ sx,
                             const float* __restrict__ tg) {
    int idx = blockIdx.x * blockDim.x + threadIdx.x;
    int cl = idx >> 14, i = idx & (N_PTS - 1);
    const float* p = cl ? tg : sx;
    float x = p[3 * i], y = p[3 * i + 1], z = p[3 * i + 2];
    int cid = (cell_coord(z) << 10) | (cell_coord(y) << 5) | cell_coord(x);
    atomicAdd(&g_cnt[cl][cid], 1);
}

__global__ __launch_bounds__(1024) void scan_kernel() {
    __shared__ int sh[1024];
    const int cl = blockIdx.x;
    const int t = threadIdx.x;
    const int base = t * 32;
    int loc[32];
    int sum = 0;
    #pragma unroll
    for (int k = 0; k < 32; k++) {
        loc[k] = g_cnt[cl][base + k];
        g_cnt[cl][base + k] = 0;          // restore invariant for next call
        sum += loc[k];
    }
    sh[t] = sum;
    __syncthreads();
    for (int off = 1; off < 1024; off <<= 1) {   // Hillis-Steele inclusive
        int v = (t >= off) ? sh[t - off] : 0;
        __syncthreads();
        sh[t] += v;
        __syncthreads();
    }
    int run = sh[t] - sum;                        // exclusive prefix
    #pragma unroll
    for (int k = 0; k < 32; k++) {
        g_start[cl][base + k] = run;
        g_cur[cl][base + k] = run;
        run += loc[k];
    }
    if (t == 1023) g_start[cl][CELLS] = run;      // == N_PTS
}

__global__ void scatter_kernel(const float* __restrict__ sx,
                               const float* __restrict__ tg) {
    int idx = blockIdx.x * blockDim.x + threadIdx.x;
    int cl = idx >> 14, i = idx & (N_PTS - 1);
    const float* p = cl ? tg : sx;
    float x = p[3 * i], y = p[3 * i + 1], z = p[3 * i + 2];
    int cid = (cell_coord(z) << 10) | (cell_coord(y) << 5) | cell_coord(x);
    int pos = atomicAdd(&g_cur[cl][cid], 1);
    g_pts[cl][pos] = make_float4(x, y, z, x * x + y * y + z * z);
}

// One query per 4-thread quad. Queries come from the cell-sorted array, so
// adjacent quads share neighborhood cells (L1 reuse, coherent branches).
__global__ __launch_bounds__(256) void search_kernel() {
    const int gtid = blockIdx.x * 256 + threadIdx.x;
    const int qcl = blockIdx.y;
    const int rcl = qcl ^ 1;
    const int qid = gtid >> 2;
    const int sub = gtid & 3;
    const unsigned qmask = 0xFu << (threadIdx.x & 28);

    const float4 q = g_pts[qcl][qid];
    const float nax = -2.0f * q.x, nay = -2.0f * q.y, naz = -2.0f * q.z;
    const float a2 = q.w;
    const int cx = cell_coord(q.x), cy = cell_coord(q.y), cz = cell_coord(q.z);

    const float4* __restrict__ ref = g_pts[rcl];
    const int* __restrict__ st = g_start[rcl];

    float m = __int_as_float(0x7f800000);

    // ---- FAST PATH: 3x3x3 neighborhood = shells 0 and 1, as 9 contiguous
    //      x-row ranges (x is the fastest grid dimension). ----
    const int xlo = max(cx - 1, 0), xhi = min(cx + 1, GRIDD - 1);
    const int ylo = max(cy - 1, 0), yhi = min(cy + 1, GRIDD - 1);
    const int zlo = max(cz - 1, 0), zhi = min(cz + 1, GRIDD - 1);
    for (int z = zlo; z <= zhi; z++) {
        for (int y = ylo; y <= yhi; y++) {
            int row = (z << 10) | (y << 5);
            int s = st[row + xlo];
            int e = st[row + xhi + 1];
            for (int p = s + sub; p < e; p += SUBQ) {
                float4 t = ref[p];
                float d = fmaf(naz, t.z, t.w);
                d = fmaf(nay, t.y, d);
                d = fmaf(nax, t.x, d);
                m = fminf(m, d);
            }
        }
    }
    m = fminf(m, __shfl_xor_sync(qmask, m, 1));
    m = fminf(m, __shfl_xor_sync(qmask, m, 2));
    float best = fmaxf(a2 + m, 0.0f);

    // After scanning all cells with Chebyshev cell-distance <= 1, any
    // unscanned point is >= 1*CELL away. Almost always: best <= CELL^2.
    if (best > CELL * CELL) {
        // ---- SLOW PATH (rare): expand Chebyshev shells r = 2, 3, ... ----
        for (int r = 2; r < GRIDD; r++) {
            for (int dz = -r; dz <= r; dz++) {
                int z = cz + dz;
                if ((unsigned)z >= GRIDD) continue;
                for (int dy = -r; dy <= r; dy++) {
                    int y = cy + dy;
                    if ((unsigned)y >= GRIDD) continue;
                    int row = (z << 10) | (y << 5);
                    bool edge = (dz == -r) | (dz == r) | (dy == -r) | (dy == r);
                    if (edge) {
                        // full x-row [cx-r, cx+r], contiguous
                        int x0 = max(cx - r, 0), x1 = min(cx + r, GRIDD - 1);
                        int s = st[row + x0], e = st[row + x1 + 1];
                        for (int p = s + sub; p < e; p += SUBQ) {
                            float4 t = ref[p];
                            float d = fmaf(naz, t.z, t.w);
                            d = fmaf(nay, t.y, d);
                            d = fmaf(nax, t.x, d);
                            m = fminf(m, d);
                        }
                    } else {
                        // only x = cx-r and x = cx+r
                        #pragma unroll
                        for (int sgn = 0; sgn < 2; sgn++) {
                            int x = sgn ? cx + r : cx - r;
                            if ((unsigned)x >= GRIDD) continue;
                            int s = st[row + x], e = st[row + x + 1];
                            for (int p = s + sub; p < e; p += SUBQ) {
                                float4 t = ref[p];
                                float d = fmaf(naz, t.z, t.w);
                                d = fmaf(nay, t.y, d);
                                d = fmaf(nax, t.x, d);
                                m = fminf(m, d);
                            }
                        }
                    }
                }
            }
            m = fminf(m, __shfl_xor_sync(qmask, m, 1));
            m = fminf(m, __shfl_xor_sync(qmask, m, 2));
            best = fmaxf(a2 + m, 0.0f);
            float bound = (float)r * CELL;
            if (best <= bound * bound) break;
        }
    }

    if (sub == 0) g_sq[qcl][qid] = sqrtf(best);
}

__global__ __launch_bounds__(1024) void reduce_kernel(float* __restrict__ out) {
    __shared__ float red[1024];
    const int tid = threadIdx.x;
    const float4* v = (const float4*)g_sq;   // 32768 floats = 8192 float4
    float s = 0.0f;
    #pragma unroll
    for (int k = 0; k < 8; k++) {
        float4 t = v[tid + k * 1024];
        s += (t.x + t.y) + (t.z + t.w);
    }
    red[tid] = s;
    __syncthreads();
    #pragma unroll
    for (int off = 512; off > 0; off >>= 1) {
        if (tid < off) red[tid] += red[tid + off];
        __syncthreads();
    }
    if (tid == 0)
        out[0] = red[0] * (5.0f / (float)N_PTS);   // (mean1 + mean2)*0.5*10
}

extern "C" void kernel_launch(void* const* d_in, const int* in_sizes, int n_in,
                              void* d_out, int out_size) {
    const float* state_x = (const float*)d_in[0];
    const float* target  = (const float*)d_in[1];

    count_kernel<<<(2 * N_PTS) / 256, 256>>>(state_x, target);
    scan_kernel<<<2, 1024>>>();
    scatter_kernel<<<(2 * N_PTS) / 256, 256>>>(state_x, target);

    dim3 sgrid((N_PTS * SUBQ) / 256, 2);
    search_kernel<<<sgrid, 256>>>();

    reduce_kernel<<<1, 1024>>>((float*)d_out);
}

// round 5
// speedup vs baseline: 2.9302x; 2.0464x over previous
#include <cuda_runtime.h>
#include <cstdint>

#define N_PTS   16384
#define GRIDD   32
#define CELLS   (GRIDD * GRIDD * GRIDD)
#define LOF     (-5.0f)
#define CELL    0.3125f
#define INVCELL 3.2f
#define SUBQ    4
#define SLOWB   64        // blocks per direction in slow kernel

// Scratch in device globals. INVARIANTS restored every call:
//  g_cnt == 0 on entry to count_kernel (load-time zero; scan restores it),
//  g_npend == 0 before search_fast appends (scan zeroes it).
__device__ int    g_cnt[2][CELLS];
__device__ int    g_cur[2][CELLS];
__device__ int    g_start[2][CELLS + 8];   // +8 pad keeps row 1 16B-aligned
__device__ float4 g_pts[2][N_PTS];         // cell-sorted: (x, y, z, |p|^2)
__device__ float  g_sq[2][N_PTS];          // sqrt(min sq dist) per query
__device__ int    g_pend[2][N_PTS];        // unresolved query ids
__device__ int    g_npend[2];
__device__ float  g_partial[8];

__device__ __forceinline__ int cell_coord(float v) {
    int c = (int)((v - LOF) * INVCELL);
    return min(max(c, 0), GRIDD - 1);
}

__global__ void count_kernel(const float* __restrict__ sx,
                             const float* __restrict__ tg) {
    int idx = blockIdx.x * blockDim.x + threadIdx.x;
    int cl = idx >> 14, i = idx & (N_PTS - 1);
    const float* p = cl ? tg : sx;
    float x = p[3 * i], y = p[3 * i + 1], z = p[3 * i + 2];
    int cid = (cell_coord(z) << 10) | (cell_coord(y) << 5) | cell_coord(x);
    atomicAdd(&g_cnt[cl][cid], 1);
}

__global__ __launch_bounds__(1024) void scan_kernel() {
    __shared__ int sh[1024];
    const int cl = blockIdx.x;
    const int t = threadIdx.x;
    int4* c4 = (int4*)&g_cnt[cl][0];
    int loc[32];
    int sum = 0;
    #pragma unroll
    for (int k = 0; k < 8; k++) {
        int4 v = c4[t * 8 + k];
        loc[4*k+0] = v.x; loc[4*k+1] = v.y; loc[4*k+2] = v.z; loc[4*k+3] = v.w;
        sum += (v.x + v.y) + (v.z + v.w);
        c4[t * 8 + k] = make_int4(0, 0, 0, 0);   // restore invariant
    }
    sh[t] = sum;
    __syncthreads();
    for (int off = 1; off < 1024; off <<= 1) {   // Hillis-Steele inclusive
        int v = (t >= off) ? sh[t - off] : 0;
        __syncthreads();
        sh[t] += v;
        __syncthreads();
    }
    int run = sh[t] - sum;                        // exclusive prefix
    int4* s4 = (int4*)&g_start[cl][0];
    int4* u4 = (int4*)&g_cur[cl][0];
    #pragma unroll
    for (int k = 0; k < 8; k++) {
        int4 w;
        w.x = run; run += loc[4*k+0];
        w.y = run; run += loc[4*k+1];
        w.z = run; run += loc[4*k+2];
        w.w = run; run += loc[4*k+3];
        s4[t * 8 + k] = w;
        u4[t * 8 + k] = w;
    }
    if (t == 1023) g_start[cl][CELLS] = run;      // == N_PTS
    if (t == 0) g_npend[cl] = 0;                  // reset pending counter
}

__global__ void scatter_kernel(const float* __restrict__ sx,
                               const float* __restrict__ tg) {
    int idx = blockIdx.x * blockDim.x + threadIdx.x;
    int cl = idx >> 14, i = idx & (N_PTS - 1);
    const float* p = cl ? tg : sx;
    float x = p[3 * i], y = p[3 * i + 1], z = p[3 * i + 2];
    int cid = (cell_coord(z) << 10) | (cell_coord(y) << 5) | cell_coord(x);
    int pos = atomicAdd(&g_cur[cl][cid], 1);
    g_pts[cl][pos] = make_float4(x, y, z, x * x + y * y + z * z);
}

// Branch-free 3x3x3 scan, one query per 4-thread quad.
// Clamped z/y rows may duplicate at grid boundaries -> scanned twice,
// harmless for min. All 18 range bounds loaded up front (high MLP).
__global__ __launch_bounds__(256) void search_fast() {
    const int gtid = blockIdx.x * 256 + threadIdx.x;
    const int qcl = blockIdx.y;
    const int rcl = qcl ^ 1;
    const int qid = gtid >> 2;
    const int sub = gtid & 3;
    const unsigned qmask = 0xFu << (threadIdx.x & 28);

    const float4 q = g_pts[qcl][qid];
    const float nax = -2.0f * q.x, nay = -2.0f * q.y, naz = -2.0f * q.z;
    const int cx = cell_coord(q.x), cy = cell_coord(q.y), cz = cell_coord(q.z);

    const float4* __restrict__ ref = g_pts[rcl];
    const int* __restrict__ st = g_start[rcl];

    const int zr0 = max(cz - 1, 0), zr2 = min(cz + 1, GRIDD - 1);
    const int yr0 = max(cy - 1, 0), yr2 = min(cy + 1, GRIDD - 1);
    const int xlo = max(cx - 1, 0), xhi = min(cx + 1, GRIDD - 1);
    int zr[3] = {zr0, cz, zr2};
    int yr[3] = {yr0, cy, yr2};

    int s9[9], e9[9];
    #pragma unroll
    for (int i = 0; i < 9; i++) {
        int row = (zr[i / 3] << 10) | (yr[i % 3] << 5);
        s9[i] = st[row + xlo];          // 18 independent loads, batched
        e9[i] = st[row + xhi + 1];
    }

    float m = __int_as_float(0x7f800000);
    #pragma unroll
    for (int i = 0; i < 9; i++) {
        int p = s9[i] + sub;
        const int e = e9[i];
        for (; p + SUBQ < e; p += 2 * SUBQ) {        // unroll x2, MLP=2
            float4 t0 = ref[p];
            float4 t1 = ref[p + SUBQ];
            float d0 = fmaf(nax, t0.x, fmaf(nay, t0.y, fmaf(naz, t0.z, t0.w)));
            float d1 = fmaf(nax, t1.x, fmaf(nay, t1.y, fmaf(naz, t1.z, t1.w)));
            m = fminf(m, fminf(d0, d1));
        }
        if (p < e) {
            float4 t = ref[p];
            float d = fmaf(nax, t.x, fmaf(nay, t.y, fmaf(naz, t.z, t.w)));
            m = fminf(m, d);
        }
    }
    m = fminf(m, __shfl_xor_sync(qmask, m, 1));
    m = fminf(m, __shfl_xor_sync(qmask, m, 2));

    if (sub == 0) {
        float best = fmaxf(q.w + m, 0.0f);
        // All cells with Chebyshev distance <= 1 scanned; anything unscanned
        // is >= CELL away. Resolved iff best <= CELL^2; else defer.
        if (best <= CELL * CELL) {
            g_sq[qcl][qid] = sqrtf(best);
        } else {
            int slot = atomicAdd(&g_npend[qcl], 1);
            g_pend[qcl][slot] = qid;
        }
    }
}

// Exact brute force for the few pending (sparse-tail) queries.
// One warp per query; warp-uniform, unroll x4 float4 loads (L2-resident).
__global__ __launch_bounds__(256) void search_slow() {
    const int qcl = blockIdx.y;
    const int rcl = qcl ^ 1;
    const int n = g_npend[qcl];
    const int wid = blockIdx.x * 8 + (threadIdx.x >> 5);
    const int lane = threadIdx.x & 31;
    const float4* __restrict__ ref = g_pts[rcl];

    for (int k = wid; k < n; k += SLOWB * 8) {
        const int qid = g_pend[qcl][k];
        const float4 q = g_pts[qcl][qid];
        const float nax = -2.0f * q.x, nay = -2.0f * q.y, naz = -2.0f * q.z;
        float m = __int_as_float(0x7f800000);
        for (int p = lane; p < N_PTS; p += 128) {
            float4 t0 = ref[p];
            float4 t1 = ref[p + 32];
            float4 t2 = ref[p + 64];
            float4 t3 = ref[p + 96];
            float d0 = fmaf(nax, t0.x, fmaf(nay, t0.y, fmaf(naz, t0.z, t0.w)));
            float d1 = fmaf(nax, t1.x, fmaf(nay, t1.y, fmaf(naz, t1.z, t1.w)));
            float d2 = fmaf(nax, t2.x, fmaf(nay, t2.y, fmaf(naz, t2.z, t2.w)));
            float d3 = fmaf(nax, t3.x, fmaf(nay, t3.y, fmaf(naz, t3.z, t3.w)));
            m = fminf(m, fminf(fminf(d0, d1), fminf(d2, d3)));
        }
        #pragma unroll
        for (int o = 16; o; o >>= 1)
            m = fminf(m, __shfl_xor_sync(0xFFFFFFFFu, m, o));
        if (lane == 0)
            g_sq[qcl][qid] = sqrtf(fmaxf(q.w + m, 0.0f));
    }
}

__global__ __launch_bounds__(1024) void reduce1_kernel() {
    __shared__ float red[1024];
    const int tid = threadIdx.x;
    const float4* v = (const float4*)g_sq;        // 8192 float4 total
    float4 t = v[blockIdx.x * 1024 + tid];
    red[tid] = (t.x + t.y) + (t.z + t.w);
    __syncthreads();
    #pragma unroll
    for (int off = 512; off > 0; off >>= 1) {
        if (tid < off) red[tid] += red[tid + off];
        __syncthreads();
    }
    if (tid == 0) g_partial[blockIdx.x] = red[0];
}

__global__ void reduce2_kernel(float* __restrict__ out) {
    float s = 0.0f;
    #pragma unroll
    for (int i = 0; i < 8; i++) s += g_partial[i];
    out[0] = s * (5.0f / (float)N_PTS);           // (mean1 + mean2)*0.5*10
}

extern "C" void kernel_launch(void* const* d_in, const int* in_sizes, int n_in,
                              void* d_out, int out_size) {
    const float* state_x = (const float*)d_in[0];
    const float* target  = (const float*)d_in[1];

    count_kernel<<<(2 * N_PTS) / 256, 256>>>(state_x, target);
    scan_kernel<<<2, 1024>>>();
    scatter_kernel<<<(2 * N_PTS) / 256, 256>>>(state_x, target);

    dim3 fgrid((N_PTS * SUBQ) / 256, 2);
    search_fast<<<fgrid, 256>>>();

    dim3 sgrid(SLOWB, 2);
    search_slow<<<sgrid, 256>>>();

    reduce1_kernel<<<8, 1024>>>();
    reduce2_kernel<<<1, 1>>>((float*)d_out);
}

// round 7
// speedup vs baseline: 5.2776x; 1.8011x over previous
#include <cuda_runtime.h>
#include <cstdint>

#define N_PTS   16384
#define GRIDD   32
#define CELLS   (GRIDD * GRIDD * GRIDD)
#define LOF     (-5.0f)
#define CELL    0.3125f
#define INVCELL 3.2f
#define SUBQ    4

// Scratch in device globals. Invariants restored every call:
//  g_cnt == 0 at count_kernel entry (load-time zero; scan restores),
//  g_rcount == 0 at reduce entry (load-time zero; last block restores).
__device__ int      g_cnt[2][CELLS];
__device__ int      g_start[2][CELLS + 8];
__device__ unsigned g_cidrank[2][N_PTS];   // (cid << 17) | rank  (UNSIGNED!)
__device__ float4   g_pts[2][N_PTS];       // cell-sorted: (x, y, z, |p|^2)
__device__ float    g_sq[2][N_PTS];        // sqrt(min sq dist) per query
__device__ float    g_partial[8];
__device__ int      g_rcount;

__device__ __forceinline__ int cell_coord(float v) {
    int c = (int)((v - LOF) * INVCELL);
    return min(max(c, 0), GRIDD - 1);
}

__global__ void count_kernel(const float* __restrict__ sx,
                             const float* __restrict__ tg) {
    int idx = blockIdx.x * blockDim.x + threadIdx.x;
    int cl = idx >> 14, i = idx & (N_PTS - 1);
    const float* p = cl ? tg : sx;
    float x = p[3 * i], y = p[3 * i + 1], z = p[3 * i + 2];
    int cid = (cell_coord(z) << 10) | (cell_coord(y) << 5) | cell_coord(x);
    unsigned rank = (unsigned)atomicAdd(&g_cnt[cl][cid], 1);
    g_cidrank[cl][i] = ((unsigned)cid << 17) | rank;   // logical, no sign bit issues
}

__global__ __launch_bounds__(1024) void scan_kernel() {
    __shared__ int sh[1024];
    const int cl = blockIdx.x;
    const int t = threadIdx.x;
    int4* c4 = (int4*)&g_cnt[cl][0];
    int loc[32];
    int sum = 0;
    #pragma unroll
    for (int k = 0; k < 8; k++) {
        int4 v = c4[t * 8 + k];
        loc[4*k+0] = v.x; loc[4*k+1] = v.y; loc[4*k+2] = v.z; loc[4*k+3] = v.w;
        sum += (v.x + v.y) + (v.z + v.w);
        c4[t * 8 + k] = make_int4(0, 0, 0, 0);   // restore invariant
    }
    sh[t] = sum;
    __syncthreads();
    for (int off = 1; off < 1024; off <<= 1) {   // Hillis-Steele inclusive
        int v = (t >= off) ? sh[t - off] : 0;
        __syncthreads();
        sh[t] += v;
        __syncthreads();
    }
    int run = sh[t] - sum;                        // exclusive prefix
    int4* s4 = (int4*)&g_start[cl][0];
    #pragma unroll
    for (int k = 0; k < 8; k++) {
        int4 w;
        w.x = run; run += loc[4*k+0];
        w.y = run; run += loc[4*k+1];
        w.z = run; run += loc[4*k+2];
        w.w = run; run += loc[4*k+3];
        s4[t * 8 + k] = w;
    }
    if (t == 1023) g_start[cl][CELLS] = run;      // == N_PTS
}

__global__ void scatter_kernel(const float* __restrict__ sx,
                               const float* __restrict__ tg) {
    int idx = blockIdx.x * blockDim.x + threadIdx.x;
    int cl = idx >> 14, i = idx & (N_PTS - 1);
    const float* p = cl ? tg : sx;
    float x = p[3 * i], y = p[3 * i + 1], z = p[3 * i + 2];
    unsigned cr = g_cidrank[cl][i];
    int pos = g_start[cl][cr >> 17] + (int)(cr & 0x1FFFFu);  // logical shift
    g_pts[cl][pos] = make_float4(x, y, z, x * x + y * y + z * z);
}

// One query per 4-thread quad; branch-free 3x3x3 fast path; rare queries
// that fail the r=1 bound are finished warp-cooperatively in the same kernel.
__global__ __launch_bounds__(256, 4) void search_kernel() {
    const int gtid = blockIdx.x * 256 + threadIdx.x;
    const int qcl = blockIdx.y;
    const int rcl = qcl ^ 1;
    const int qid = gtid >> 2;
    const int sub = gtid & 3;
    const int lane = threadIdx.x & 31;
    const unsigned qmask = 0xFu << (threadIdx.x & 28);

    const float4 q = g_pts[qcl][qid];
    const float nax = -2.0f * q.x, nay = -2.0f * q.y, naz = -2.0f * q.z;
    const int cx = cell_coord(q.x), cy = cell_coord(q.y), cz = cell_coord(q.z);

    const float4* __restrict__ ref = g_pts[rcl];
    const int* __restrict__ st = g_start[rcl];

    // ---- fast path: 3x3x3 neighborhood as 9 contiguous x-row ranges ----
    const int xlo = max(cx - 1, 0), xhi = min(cx + 1, GRIDD - 1);
    int zr[3] = {max(cz - 1, 0), cz, min(cz + 1, GRIDD - 1)};
    int yr[3] = {max(cy - 1, 0), cy, min(cy + 1, GRIDD - 1)};

    int s9[9], e9[9];
    #pragma unroll
    for (int i = 0; i < 9; i++) {
        int row = (zr[i / 3] << 10) | (yr[i % 3] << 5);
        s9[i] = st[row + xlo];
        e9[i] = st[row + xhi + 1];
    }

    float m = __int_as_float(0x7f800000);
    #pragma unroll
    for (int i = 0; i < 9; i++) {
        int p = s9[i] + sub;
        const int e = e9[i];
        for (; p + SUBQ < e; p += 2 * SUBQ) {
            float4 t0 = ref[p];
            float4 t1 = ref[p + SUBQ];
            float d0 = fmaf(nax, t0.x, fmaf(nay, t0.y, fmaf(naz, t0.z, t0.w)));
            float d1 = fmaf(nax, t1.x, fmaf(nay, t1.y, fmaf(naz, t1.z, t1.w)));
            m = fminf(m, fminf(d0, d1));
        }
        if (p < e) {
            float4 t = ref[p];
            m = fminf(m, fmaf(nax, t.x, fmaf(nay, t.y, fmaf(naz, t.z, t.w))));
        }
    }
    m = fminf(m, __shfl_xor_sync(qmask, m, 1));
    m = fminf(m, __shfl_xor_sync(qmask, m, 2));
    float best = fmaxf(q.w + m, 0.0f);

    // all Chebyshev<=1 cells scanned -> unscanned points >= CELL away
    bool unresolved = best > CELL * CELL;
    unsigned pmask = __ballot_sync(0xFFFFFFFFu, unresolved && sub == 0);
    if (sub == 0 && !unresolved) g_sq[qcl][qid] = sqrtf(best);

    // ---- rare path: whole warp finishes each pending query together ----
    while (pmask) {
        const int src = __ffs(pmask) - 1;
        pmask &= pmask - 1;
        const float bqx = __shfl_sync(0xFFFFFFFFu, q.x, src);
        const float bqy = __shfl_sync(0xFFFFFFFFu, q.y, src);
        const float bqz = __shfl_sync(0xFFFFFFFFu, q.z, src);
        const float bqw = __shfl_sync(0xFFFFFFFFu, q.w, src);
        float mm = __shfl_sync(0xFFFFFFFFu, m, src);
        const float bax = -2.0f * bqx, bay = -2.0f * bqy, baz = -2.0f * bqz;
        const int bcx = cell_coord(bqx), bcy = cell_coord(bqy),
                  bcz = cell_coord(bqz);

        float bst;
        for (int r = 2;; r++) {
            // scan full cube radius r (rescans inner cells; harmless for min)
            int x0 = max(bcx - r, 0), x1 = min(bcx + r, GRIDD - 1);
            int y0 = max(bcy - r, 0), y1 = min(bcy + r, GRIDD - 1);
            int z0 = max(bcz - r, 0), z1 = min(bcz + r, GRIDD - 1);
            int ny = y1 - y0 + 1;
            int nrows = (z1 - z0 + 1) * ny;
            for (int rr = lane; rr < nrows; rr += 32) {
                int zz = z0 + rr / ny;
                int yy = y0 + rr % ny;
                int row = (zz << 10) | (yy << 5);
                int s = st[row + x0], e = st[row + x1 + 1];
                for (int p = s; p < e; p++) {
                    float4 t = ref[p];
                    float d = fmaf(bax, t.x,
                              fmaf(bay, t.y, fmaf(baz, t.z, t.w)));
                    mm = fminf(mm, d);
                }
            }
            #pragma unroll
            for (int o = 16; o; o >>= 1)
                mm = fminf(mm, __shfl_xor_sync(0xFFFFFFFFu, mm, o));
            bst = fmaxf(bqw + mm, 0.0f);
            float bnd = (float)r * CELL;
            bool full = (x0 == 0) & (y0 == 0) & (z0 == 0) &
                        (x1 == GRIDD - 1) & (y1 == GRIDD - 1) &
                        (z1 == GRIDD - 1);
            if (bst <= bnd * bnd || full) break;
        }
        if (lane == src) g_sq[qcl][qid] = sqrtf(bst);
    }
}

__global__ __launch_bounds__(1024) void reduce_kernel(float* __restrict__ out) {
    __shared__ float red[1024];
    const int tid = threadIdx.x;
    const float4* v = (const float4*)g_sq;        // 8192 float4 total
    float4 t = v[blockIdx.x * 1024 + tid];
    red[tid] = (t.x + t.y) + (t.z + t.w);
    __syncthreads();
    #pragma unroll
    for (int off = 512; off > 0; off >>= 1) {
        if (tid < off) red[tid] += red[tid + off];
        __syncthreads();
    }
    if (tid == 0) {
        g_partial[blockIdx.x] = red[0];
        __threadfence();
        if (atomicAdd(&g_rcount, 1) == 7) {       // last block finishes
            float s = 0.0f;
            volatile float* gp = g_partial;        // must see peers' writes
            #pragma unroll
            for (int i = 0; i < 8; i++) s += gp[i];  // fixed order
            out[0] = s * (5.0f / (float)N_PTS);   // (mean1 + mean2)*0.5*10
            g_rcount = 0;                          // restore invariant
        }
    }
}

extern "C" void kernel_launch(void* const* d_in, const int* in_sizes, int n_in,
                              void* d_out, int out_size) {
    const float* state_x = (const float*)d_in[0];
    const float* target  = (const float*)d_in[1];

    count_kernel<<<(2 * N_PTS) / 256, 256>>>(state_x, target);
    scan_kernel<<<2, 1024>>>();
    scatter_kernel<<<(2 * N_PTS) / 256, 256>>>(state_x, target);

    dim3 sgrid((N_PTS * SUBQ) / 256, 2);
    search_kernel<<<sgrid, 256>>>();

    reduce_kernel<<<8, 1024>>>((float*)d_out);
}